// round 9
// baseline (speedup 1.0000x reference)
#include <cuda_runtime.h>
#include <cuda_bf16.h>

// CRF NLL: out = -(sum_b (score_b - partition_b)),  B=512, S=1024, T=32.
//
// Bidirectional linear-domain recurrence with power-of-2 rescaling, BOTH
// directions interleaved in ONE warp (1 warp per batch, 1 warp per SMSP):
//   forward : alpha_s = D(e_s) M^T alpha_{s-1},  s = 1..512
//   backward: g_{s-1} = M (e_s ∘ g_s),           s = 1023..513  (g_1023 = exp(end))
//   Z = alpha_512 · g_512
// Each side tracked as v * 2^off, per-step scale 2^-k with k = exponent of a
// one-step-stale shuffled component (off the critical chain). One log at end.
// tags buffer is int32 on device (JAX x64-disabled downcast of jnp.int64).

#define BB 512
#define SS 1024
#define TT 32
#define PD 4
#define LN2F 0.6931471805599453f

__device__ float    g_partial[BB];
__device__ unsigned g_ctr = 0;

__device__ __forceinline__ float warp_sum(float v) {
#pragma unroll
    for (int o = 16; o; o >>= 1) v += __shfl_xor_sync(0xFFFFFFFFu, v, o);
    return v;
}

__device__ __forceinline__ float matvec32(const float* __restrict__ buf,
                                          const float* __restrict__ Mreg) {
    const float4* pb = (const float4*)buf;
    float acc[8];
#pragma unroll
    for (int g = 0; g < 8; g++) {
        float4 v = pb[g];
        acc[g] = fmaf(v.x, Mreg[4 * g + 0],
                 fmaf(v.y, Mreg[4 * g + 1],
                 fmaf(v.z, Mreg[4 * g + 2], v.w * Mreg[4 * g + 3])));
    }
    return ((acc[0] + acc[1]) + (acc[2] + acc[3]))
         + ((acc[4] + acc[5]) + (acc[6] + acc[7]));
}

__global__ void __launch_bounds__(128, 1) crf_main(
    const float* __restrict__ em, const int* __restrict__ tags,
    const float* __restrict__ mask, const float* __restrict__ trans,
    const float* __restrict__ startt, const float* __restrict__ endt,
    float* __restrict__ out)
{
    __shared__ __align__(16) float spF[4][2][TT];  // fwd state ping-pong
    __shared__ __align__(16) float spB[4][2][TT];  // bwd (e∘g) ping-pong
    __shared__ float tb[4][TT][33];                // transpose scratch

    const int w    = threadIdx.x >> 5;
    const int lane = threadIdx.x & 31;
    const int b    = blockIdx.x * 4 + w;           // one warp == one batch
    const size_t embase = (size_t)b * SS * TT;

    // M = exp(trans): column `lane` for fwd (coalesced), row `lane` for bwd
    // (via padded shared transpose, conflict-free).
    float Mcol[TT], Mrow[TT];
#pragma unroll
    for (int i = 0; i < TT; i++) {
        Mcol[i] = __expf(trans[i * TT + lane]);
        tb[w][i][lane] = Mcol[i];
    }
    __syncwarp();
#pragma unroll
    for (int i = 0; i < TT; i++) Mrow[i] = tb[w][lane][i];

    // Prefetch pipelines. Step n: fwd si = 1+n (n=0..511 real);
    // bwd si = 1023-n (n=0..510 real, n=511 masked dummy).
    float efF[PD], mfF[PD], efB[PD], mfB[PD];
#pragma unroll
    for (int u = 0; u < PD; u++) {
        int siF = 1 + u, siB = 1023 - u;
        efF[u] = em[embase + (size_t)siF * TT + lane];
        mfF[u] = mask[b * SS + siF];
        efB[u] = em[embase + (size_t)siB * TT + lane];
        mfB[u] = mask[b * SS + siB];
    }
    float exF = __expf(efF[0]), exB = __expf(efB[0]);
    float avF = 1.0f, avB = 1.0f;
    int offF = 0, offB = 0;
    int wb = 0;

    float stF = __expf(startt[lane] + em[embase + lane]);  // alpha0 (linear)
    float stB = __expf(endt[lane]);                        // g_1023

#pragma unroll 1
    for (int n0 = 0; n0 < 512; n0 += PD) {
#pragma unroll
        for (int u = 0; u < PD; u++) {
            const int n = n0 + u;

            // Stale-exponent scales (no MUFU, off chain)
            unsigned eF = (__float_as_uint(avF) >> 23) & 0xFFu;
            unsigned eB = (__float_as_uint(avB) >> 23) & 0xFFu;
            int kF = (int)eF - 127, kB = (int)eB - 127;
            float scF = __uint_as_float((254u - eF) << 23);
            float scB = __uint_as_float((254u - eB) << 23);
            float emscF = exF * scF;
            float hB    = stB * (exB * scB);   // (e ∘ g), rescaled
            float mF = mfF[u], mB = mfB[u];

            // Both stores, ONE sync (double-buffered; no trailing sync needed)
            spF[w][wb][lane] = stF;
            spB[w][wb][lane] = hB;
            __syncwarp();

            // Prefetch step n+PD into slot u
            {
                int np = n + PD;
                bool okF = np < 512, okB = np < 511;
                int siF = 1 + np, siB = 1023 - np;
                efF[u] = okF ? em[embase + (size_t)siF * TT + lane] : 0.f;
                mfF[u] = okF ? mask[b * SS + siF] : 0.f;
                efB[u] = okB ? em[embase + (size_t)siB * TT + lane] : 0.f;
                mfB[u] = okB ? mask[b * SS + siB] : 0.f;
            }

            // Two independent matvecs (interleave for latency hiding)
            float AF = matvec32(spF[w][wb], Mcol);   // Σ_i p_i M[i][lane]
            float AB = matvec32(spB[w][wb], Mrow);   // Σ_j M[lane][j] h_j

            float avFn = __shfl_sync(0xFFFFFFFFu, AF, 0);
            float avBn = __shfl_sync(0xFFFFFFFFu, AB, 0);

            float pn = AF * emscF;
            bool uF = (mF != 0.f), uB = (mB != 0.f);
            stF = uF ? pn : stF;   offF += uF ? kF : 0;
            stB = uB ? AB : stB;   offB += uB ? kB : 0;

            wb ^= 1; avF = avFn; avB = avBn;
            exF = __expf(efF[(u + 1) & (PD - 1)]);
            exB = __expf(efB[(u + 1) & (PD - 1)]);
        }
    }

    // partition_b = ln(alpha_512 · g_512) + (offF+offB)·ln2
    float dot = warp_sum(stF * stB);
    float partition = logf(dot) + (float)(offF + offB) * LN2F;

    // ---- gold-path score, lanes strided over sequence positions ----
    float sc = 0.f, ms = 0.f;
    const int* tg = tags + (size_t)b * SS;
#pragma unroll 4
    for (int it = 0; it < SS / 32; it++) {
        int s  = it * 32 + lane;
        int tc = tg[s];
        float mm = mask[b * SS + s];
        ms += mm;
        if (s == 0) {
            sc += startt[tc] + em[embase + tc];
        } else {
            int tp = tg[s - 1];
            sc += (em[embase + (size_t)s * TT + tc] + trans[tp * TT + tc]) * mm;
        }
    }
    sc = warp_sum(sc); ms = warp_sum(ms);

    if (lane == 0) {
        int last = (int)ms - 1;
        g_partial[b] = (sc + endt[tg[last]]) - partition;
        __threadfence();
    }
    __syncthreads();

    // ---- last-CTA-done final reduction (no separate kernel) ----
    if (w == 0) {
        unsigned done = 0;
        if (lane == 0) done = atomicAdd(&g_ctr, 1);
        done = __shfl_sync(0xFFFFFFFFu, done, 0);
        if (done == gridDim.x - 1) {
            __threadfence();
            float v = 0.f;
#pragma unroll
            for (int i = 0; i < BB / 32; i++) v += g_partial[lane + i * 32];
            v = warp_sum(v);
            if (lane == 0) { out[0] = -v; g_ctr = 0; }   // reset for graph replay
        }
    }
}

extern "C" void kernel_launch(void* const* d_in, const int* in_sizes, int n_in,
                              void* d_out, int out_size) {
    const float* em    = (const float*)d_in[0];
    const int*   tags  = (const int*)d_in[1];
    const float* mask  = (const float*)d_in[2];
    const float* trans = (const float*)d_in[3];
    const float* st    = (const float*)d_in[4];
    const float* en    = (const float*)d_in[5];
    (void)in_sizes; (void)n_in; (void)out_size;

    crf_main<<<BB / 4, 128>>>(em, tags, mask, trans, st, en, (float*)d_out);
}